// round 1
// baseline (speedup 1.0000x reference)
#include <cuda_runtime.h>
#include <cstdint>

// Problem dims (fixed by the dataset)
#define BB  256   // batch
#define TT  256   // timesteps
#define IND 128   // input dim
#define SS  1024  // state dim

// Scratch: __device__ globals (no allocations allowed in kernel_launch).
// g_ext: input projection for all timesteps, stored [t][b][s] for scan locality.
__device__ float g_ext[(size_t)TT * BB * SS];   // 268 MB
__device__ float g_s1[BB * SS];                 // state ping
__device__ float g_s2[BB * SS];                 // state pong

__global__ void zero_kernel(float* __restrict__ p, int n) {
    int i = blockIdx.x * blockDim.x + threadIdx.x;
    if (i < n) p[i] = 0.0f;
}

// Generic C[m][n] = act( sum_k (A[m][k] (+Ext[m][k])) * W[n][k] + bias[n] )
// A, W row-major with row length K. Tile: BM=32, BN=64, BK=16, 256 threads,
// 2x4 micro-tile per thread, register prefetch of next K-tile.
// PROJ=true remaps the output row m=(b*T+t) into g_ext's [t][b][s] layout.
template <int K, bool RELU, bool PROJ>
__global__ __launch_bounds__(256) void gemm_kernel(
    const float* __restrict__ A0, const float* __restrict__ Ext,
    const float* __restrict__ W,  const float* __restrict__ bias,
    float* __restrict__ Out)
{
    const int m0 = blockIdx.x * 32;
    const int n0 = blockIdx.y * 64;

    __shared__ float As[16][34];   // [k][m], padded
    __shared__ float Bs[16][68];   // [k][n], padded (row stride 272B = 16B aligned)

    const int tid = threadIdx.x;
    // A loader: 32 rows x 16 k, 8 threads per row, float2 each
    const int ar = tid >> 3;           // 0..31
    const int ac = (tid & 7) << 1;     // 0,2,...,14
    // B loader: 64 rows x 16 k, 4 threads per row, float4 each
    const int br = tid >> 2;           // 0..63
    const int bq = (tid & 3) << 2;     // 0,4,8,12
    // Compute mapping: 16x16 threads -> rows 2*ty+{0,1}, cols 4*tx..4*tx+3
    const int ty = tid >> 4;
    const int tx = tid & 15;

    const float* aptr = A0 + (size_t)(m0 + ar) * K + ac;
    const float* eptr = (!PROJ && Ext) ? (Ext + (size_t)(m0 + ar) * K + ac) : nullptr;
    const float* wptr = W + (size_t)(n0 + br) * K + bq;

    float2 av = *reinterpret_cast<const float2*>(aptr);
    if (eptr) {
        float2 ev = *reinterpret_cast<const float2*>(eptr);
        av.x += ev.x; av.y += ev.y;
    }
    float4 bv = *reinterpret_cast<const float4*>(wptr);

    float acc[2][4] = {};

    for (int k0 = 0; k0 < K; k0 += 16) {
        As[ac][ar]     = av.x;
        As[ac + 1][ar] = av.y;
        Bs[bq][br]     = bv.x;
        Bs[bq + 1][br] = bv.y;
        Bs[bq + 2][br] = bv.z;
        Bs[bq + 3][br] = bv.w;
        __syncthreads();

        // Prefetch next K-tile into registers while computing this one.
        if (k0 + 16 < K) {
            av = *reinterpret_cast<const float2*>(aptr + k0 + 16);
            if (eptr) {
                float2 ev = *reinterpret_cast<const float2*>(eptr + k0 + 16);
                av.x += ev.x; av.y += ev.y;
            }
            bv = *reinterpret_cast<const float4*>(wptr + k0 + 16);
        }

        #pragma unroll
        for (int kk = 0; kk < 16; kk++) {
            float2 a = *reinterpret_cast<const float2*>(&As[kk][ty << 1]);
            float4 b = *reinterpret_cast<const float4*>(&Bs[kk][tx << 2]);
            acc[0][0] += a.x * b.x; acc[0][1] += a.x * b.y;
            acc[0][2] += a.x * b.z; acc[0][3] += a.x * b.w;
            acc[1][0] += a.y * b.x; acc[1][1] += a.y * b.y;
            acc[1][2] += a.y * b.z; acc[1][3] += a.y * b.w;
        }
        __syncthreads();
    }

    float4 bb = *reinterpret_cast<const float4*>(bias + n0 + (tx << 2));
    #pragma unroll
    for (int i = 0; i < 2; i++) {
        float4 o;
        o.x = acc[i][0] + bb.x;
        o.y = acc[i][1] + bb.y;
        o.z = acc[i][2] + bb.z;
        o.w = acc[i][3] + bb.w;
        if (RELU) {
            o.x = fmaxf(o.x, 0.0f); o.y = fmaxf(o.y, 0.0f);
            o.z = fmaxf(o.z, 0.0f); o.w = fmaxf(o.w, 0.0f);
        }
        const int m = m0 + (ty << 1) + i;
        size_t off;
        if (PROJ) {
            // m = b*T + t  ->  write to ext[t][b][n]
            const int b = m >> 8;     // m / TT  (TT == 256)
            const int t = m & 255;    // m % TT
            off = ((size_t)t * BB + b) * SS + (size_t)(n0 + (tx << 2));
        } else {
            off = (size_t)m * SS + (size_t)(n0 + (tx << 2));
        }
        *reinterpret_cast<float4*>(Out + off) = o;
    }
}

// out[b][t][s] = s_final[b][s], vectorized float4.
__global__ void broadcast_kernel(const float4* __restrict__ s, float4* __restrict__ out) {
    const int idx = blockIdx.x * blockDim.x + threadIdx.x;  // 0 .. B*T*S/4-1
    const int b  = idx >> 16;   // / (TT*SS/4) = 65536
    const int s4 = idx & 255;   // % (SS/4)   = 256
    out[idx] = s[(b << 8) + s4];
}

extern "C" void kernel_launch(void* const* d_in, const int* in_sizes, int n_in,
                              void* d_out, int out_size)
{
    const float* x      = (const float*)d_in[0];  // [B,T,IN]
    const float* W_in   = (const float*)d_in[1];  // [S,IN]
    const float* b_in   = (const float*)d_in[2];  // [S]
    const float* W_rec  = (const float*)d_in[3];  // [S,S]
    const float* b_rec  = (const float*)d_in[4];  // [S]
    const float* W_rec2 = (const float*)d_in[5];  // [S,S]
    const float* b_rec2 = (const float*)d_in[6];  // [S]
    float* out = (float*)d_out;

    float *s1, *s2, *ext;
    cudaGetSymbolAddress((void**)&s1,  g_s1);
    cudaGetSymbolAddress((void**)&s2,  g_s2);
    cudaGetSymbolAddress((void**)&ext, g_ext);

    // state0 = 0
    zero_kernel<<<(BB * SS + 255) / 256, 256>>>(s1, BB * SS);

    // Phase 1: ext[t][b][s] = x[b][t][:] @ W_in^T + b_in
    {
        dim3 grid((BB * TT) / 32, SS / 64);
        gemm_kernel<IND, false, true><<<grid, 256>>>(x, nullptr, W_in, b_in, ext);
    }

    // Phase 2: sequential scan, 2 fused bias+ReLU GEMMs per step
    {
        dim3 grid(BB / 32, SS / 64);
        for (int t = 0; t < TT; t++) {
            gemm_kernel<SS, true, false><<<grid, 256>>>(
                s1, ext + (size_t)t * BB * SS, W_rec, b_rec, s2);
            gemm_kernel<SS, true, false><<<grid, 256>>>(
                s2, nullptr, W_rec2, b_rec2, s1);
        }
    }

    // Phase 3: broadcast final state to all timesteps
    broadcast_kernel<<<(BB * TT * SS / 4) / 256, 256>>>(
        (const float4*)s1, (float4*)out);
}

// round 3
// speedup vs baseline: 3.2703x; 3.2703x over previous
#include <cuda_runtime.h>
#include <cuda_bf16.h>
#include <cstdint>

// Problem dims
#define BB  256
#define TT  256
#define IND 128
#define SS  1024

// ---------------- scratch (__device__ globals) ------------------------------
__device__ float g_ext[(size_t)TT * BB * SS];            // [t][b][s] fp32
__device__ __nv_bfloat16 g_sAh[BB * SS], g_sAl[BB * SS];
__device__ __nv_bfloat16 g_sBh[BB * SS], g_sBl[BB * SS];
__device__ __nv_bfloat16 g_W1h[SS * SS], g_W1l[SS * SS];
__device__ __nv_bfloat16 g_W2h[SS * SS], g_W2l[SS * SS];

// ---------------- helpers ---------------------------------------------------
__device__ __forceinline__ uint32_t smem_u32(const void* p) {
    uint32_t a;
    asm("{ .reg .u64 t; cvta.to.shared.u64 t, %1; cvt.u32.u64 %0, t; }" : "=r"(a) : "l"(p));
    return a;
}
__device__ __forceinline__ void cp16(uint32_t dst, const void* src) {
    asm volatile("cp.async.cg.shared.global [%0], [%1], 16;" :: "r"(dst), "l"(src));
}
__device__ __forceinline__ void cp_commit() { asm volatile("cp.async.commit_group;"); }
__device__ __forceinline__ void cp_wait0()  { asm volatile("cp.async.wait_group 0;"); }
__device__ __forceinline__ void cp_wait1()  { asm volatile("cp.async.wait_group 1;"); }

// mma.sync m16n8k16 row.col f32 += bf16*bf16 (base PTX feature, works on sm_103)
__device__ __forceinline__ void mma16816(float* c, uint32_t a0, uint32_t a1,
                                         uint32_t a2, uint32_t a3,
                                         uint32_t b0, uint32_t b1) {
    asm volatile(
        "mma.sync.aligned.m16n8k16.row.col.f32.bf16.bf16.f32 "
        "{%0,%1,%2,%3}, {%4,%5,%6,%7}, {%8,%9}, {%0,%1,%2,%3};"
        : "+f"(c[0]), "+f"(c[1]), "+f"(c[2]), "+f"(c[3])
        : "r"(a0), "r"(a1), "r"(a2), "r"(a3), "r"(b0), "r"(b1));
}

// ---------------- layer GEMM (mma.sync, bf16 hi/lo split) -------------------
// O[m,n] = relu( sum_k (Ah+Al)[m,k]*(Wh+Wl)[n,k] + bias[n] ) (+ ext_next[m,n])
// CTA tile 32x64, K chunk 64, 2-stage cp.async pipeline, 128 threads (4 warps),
// warp tile 16x32. SMEM row pitch 144B -> conflict-free fragment loads.
#define M_TILE 32
#define N_TILE 64
#define KC     64
#define NCHUNK (SS / KC)          // 16
#define PITCH_B  144              // bytes per 64-elem bf16 row (128 + 16 pad)
#define PITCH_E  72               // elements
#define A_HI 0
#define A_LO (32 * PITCH_B)       // 4608
#define B_HI (2 * 32 * PITCH_B)   // 9216
#define B_LO (B_HI + 64 * PITCH_B)
#define STAGE_BYTES (B_LO + 64 * PITCH_B)   // 27648
#define SM_TOTAL (2 * STAGE_BYTES)          // 55296

__device__ __forceinline__ void load_chunk(
    uint32_t st, int kc0, int tid, int m0, int n0,
    const __nv_bfloat16* __restrict__ Ah, const __nv_bfloat16* __restrict__ Al,
    const __nv_bfloat16* __restrict__ Wh, const __nv_bfloat16* __restrict__ Wl)
{
    #pragma unroll
    for (int i = 0; i < 12; i++) {
        int u = tid + i * 128;                 // 0..1535
        const __nv_bfloat16* srcb;
        uint32_t dstb;
        if (u < 512) {                         // A hi (0..255) / A lo (256..511)
            int sel = u >> 8, v = u & 255;
            int row = v >> 3, cu = v & 7;
            srcb = (sel ? Al : Ah) + (size_t)(m0 + row) * SS + kc0 + cu * 8;
            dstb = st + (sel ? A_LO : A_HI) + row * PITCH_B + cu * 16;
        } else {                               // B hi (512..1023) / B lo (1024..1535)
            int sel = (u - 512) >> 9, v = (u - 512) & 511;
            int row = v >> 3, cu = v & 7;
            srcb = (sel ? Wl : Wh) + (size_t)(n0 + row) * SS + kc0 + cu * 8;
            dstb = st + (sel ? B_LO : B_HI) + row * PITCH_B + cu * 16;
        }
        cp16(dstb, srcb);
    }
    cp_commit();
}

__global__ __launch_bounds__(128) void layer_kernel(
    const __nv_bfloat16* __restrict__ Ah, const __nv_bfloat16* __restrict__ Al,
    const __nv_bfloat16* __restrict__ Wh, const __nv_bfloat16* __restrict__ Wl,
    const float* __restrict__ bias, const float* __restrict__ ext_next,
    __nv_bfloat16* __restrict__ Oh, __nv_bfloat16* __restrict__ Ol)
{
    extern __shared__ char smem[];
    const uint32_t sb = smem_u32(smem);
    const int tid = threadIdx.x;
    const int wid = tid >> 5, lane = tid & 31;
    const int g = lane >> 2, t = lane & 3;
    const int wm = (wid >> 1) * 16;            // warp row offset (0/16)
    const int wn = (wid & 1) * 32;             // warp col offset (0/32)
    const int m0 = blockIdx.x * M_TILE, n0 = blockIdx.y * N_TILE;

    float acc[4][4] = {};                      // 4 n8-tiles x {c0,c1,c2,c3}

    load_chunk(sb, 0, tid, m0, n0, Ah, Al, Wh, Wl);

    #pragma unroll 1
    for (int c = 0; c < NCHUNK; c++) {
        if (c + 1 < NCHUNK) {
            load_chunk(sb + ((c + 1) & 1) * STAGE_BYTES, (c + 1) * KC,
                       tid, m0, n0, Ah, Al, Wh, Wl);
            cp_wait1();
        } else {
            cp_wait0();
        }
        __syncthreads();

        const char* stg = smem + (c & 1) * STAGE_BYTES;
        const __nv_bfloat16* pAh = (const __nv_bfloat16*)(stg + A_HI);
        const __nv_bfloat16* pAl = (const __nv_bfloat16*)(stg + A_LO);
        const __nv_bfloat16* pBh = (const __nv_bfloat16*)(stg + B_HI);
        const __nv_bfloat16* pBl = (const __nv_bfloat16*)(stg + B_LO);

        #pragma unroll
        for (int ks = 0; ks < 4; ks++) {
            const int kb = ks * 16 + t * 2;
            const int ar0 = (wm + g) * PITCH_E + kb;
            const int ar1 = ar0 + 8 * PITCH_E;
            uint32_t ah0 = *(const uint32_t*)(pAh + ar0);
            uint32_t ah1 = *(const uint32_t*)(pAh + ar1);
            uint32_t ah2 = *(const uint32_t*)(pAh + ar0 + 8);
            uint32_t ah3 = *(const uint32_t*)(pAh + ar1 + 8);
            uint32_t al0 = *(const uint32_t*)(pAl + ar0);
            uint32_t al1 = *(const uint32_t*)(pAl + ar1);
            uint32_t al2 = *(const uint32_t*)(pAl + ar0 + 8);
            uint32_t al3 = *(const uint32_t*)(pAl + ar1 + 8);
            #pragma unroll
            for (int j = 0; j < 4; j++) {
                const int br = (wn + j * 8 + g) * PITCH_E + kb;
                uint32_t bh0 = *(const uint32_t*)(pBh + br);
                uint32_t bh1 = *(const uint32_t*)(pBh + br + 8);
                uint32_t bl0 = *(const uint32_t*)(pBl + br);
                uint32_t bl1 = *(const uint32_t*)(pBl + br + 8);
                mma16816(acc[j], ah0, ah1, ah2, ah3, bh0, bh1);
                mma16816(acc[j], ah0, ah1, ah2, ah3, bl0, bl1);
                mma16816(acc[j], al0, al1, al2, al3, bh0, bh1);
            }
        }
        __syncthreads();
    }

    // Epilogue: bias + relu (+ ext_next) + hi/lo split + store
    const int row0 = m0 + wm + g;
    const int row1 = row0 + 8;
    #pragma unroll
    for (int j = 0; j < 4; j++) {
        const int col = n0 + wn + j * 8 + t * 2;
        float2 bb = *(const float2*)(bias + col);
        float v00 = fmaxf(acc[j][0] + bb.x, 0.0f);
        float v01 = fmaxf(acc[j][1] + bb.y, 0.0f);
        float v10 = fmaxf(acc[j][2] + bb.x, 0.0f);
        float v11 = fmaxf(acc[j][3] + bb.y, 0.0f);
        if (ext_next) {
            float2 e0 = *(const float2*)(ext_next + (size_t)row0 * SS + col);
            float2 e1 = *(const float2*)(ext_next + (size_t)row1 * SS + col);
            v00 += e0.x; v01 += e0.y; v10 += e1.x; v11 += e1.y;
        }
        __nv_bfloat16 h00 = __float2bfloat16(v00), h01 = __float2bfloat16(v01);
        __nv_bfloat16 h10 = __float2bfloat16(v10), h11 = __float2bfloat16(v11);
        __nv_bfloat16 l00 = __float2bfloat16(v00 - __bfloat162float(h00));
        __nv_bfloat16 l01 = __float2bfloat16(v01 - __bfloat162float(h01));
        __nv_bfloat16 l10 = __float2bfloat16(v10 - __bfloat162float(h10));
        __nv_bfloat16 l11 = __float2bfloat16(v11 - __bfloat162float(h11));
        *(uint32_t*)(Oh + (size_t)row0 * SS + col) =
            (uint32_t)__bfloat16_as_ushort(h00) | ((uint32_t)__bfloat16_as_ushort(h01) << 16);
        *(uint32_t*)(Oh + (size_t)row1 * SS + col) =
            (uint32_t)__bfloat16_as_ushort(h10) | ((uint32_t)__bfloat16_as_ushort(h11) << 16);
        *(uint32_t*)(Ol + (size_t)row0 * SS + col) =
            (uint32_t)__bfloat16_as_ushort(l00) | ((uint32_t)__bfloat16_as_ushort(l01) << 16);
        *(uint32_t*)(Ol + (size_t)row1 * SS + col) =
            (uint32_t)__bfloat16_as_ushort(l10) | ((uint32_t)__bfloat16_as_ushort(l11) << 16);
    }
}

// ---------------- fp32 input projection (writes ext[t][b][s]) ---------------
template <int K>
__global__ __launch_bounds__(256) void proj_kernel(
    const float* __restrict__ A0, const float* __restrict__ W,
    const float* __restrict__ bias, float* __restrict__ Out)
{
    const int m0 = blockIdx.x * 32;
    const int n0 = blockIdx.y * 64;
    __shared__ float As[16][34];
    __shared__ float Bs[16][68];
    const int tid = threadIdx.x;
    const int ar = tid >> 3, ac = (tid & 7) << 1;
    const int br = tid >> 2, bq = (tid & 3) << 2;
    const int ty = tid >> 4, tx = tid & 15;

    const float* aptr = A0 + (size_t)(m0 + ar) * K + ac;
    const float* wptr = W + (size_t)(n0 + br) * K + bq;
    float2 av = *reinterpret_cast<const float2*>(aptr);
    float4 bv = *reinterpret_cast<const float4*>(wptr);
    float acc[2][4] = {};

    for (int k0 = 0; k0 < K; k0 += 16) {
        As[ac][ar] = av.x; As[ac + 1][ar] = av.y;
        Bs[bq][br] = bv.x; Bs[bq + 1][br] = bv.y;
        Bs[bq + 2][br] = bv.z; Bs[bq + 3][br] = bv.w;
        __syncthreads();
        if (k0 + 16 < K) {
            av = *reinterpret_cast<const float2*>(aptr + k0 + 16);
            bv = *reinterpret_cast<const float4*>(wptr + k0 + 16);
        }
        #pragma unroll
        for (int kk = 0; kk < 16; kk++) {
            float2 a = *reinterpret_cast<const float2*>(&As[kk][ty << 1]);
            float4 b = *reinterpret_cast<const float4*>(&Bs[kk][tx << 2]);
            acc[0][0] += a.x * b.x; acc[0][1] += a.x * b.y;
            acc[0][2] += a.x * b.z; acc[0][3] += a.x * b.w;
            acc[1][0] += a.y * b.x; acc[1][1] += a.y * b.y;
            acc[1][2] += a.y * b.z; acc[1][3] += a.y * b.w;
        }
        __syncthreads();
    }
    float4 bb = *reinterpret_cast<const float4*>(bias + n0 + (tx << 2));
    #pragma unroll
    for (int i = 0; i < 2; i++) {
        float4 o;
        o.x = acc[i][0] + bb.x; o.y = acc[i][1] + bb.y;
        o.z = acc[i][2] + bb.z; o.w = acc[i][3] + bb.w;
        const int m = m0 + (ty << 1) + i;
        const int b = m >> 8, t = m & 255;            // m = b*T + t
        size_t off = ((size_t)t * BB + b) * SS + (size_t)(n0 + (tx << 2));
        *reinterpret_cast<float4*>(Out + off) = o;
    }
}

// ---------------- hi/lo split of a float array ------------------------------
__global__ void split_kernel(const float4* __restrict__ in,
                             uint2* __restrict__ hi, uint2* __restrict__ lo, int n4)
{
    int i = blockIdx.x * blockDim.x + threadIdx.x;
    if (i >= n4) return;
    float4 v = in[i];
    __nv_bfloat16 h0 = __float2bfloat16(v.x), h1 = __float2bfloat16(v.y);
    __nv_bfloat16 h2 = __float2bfloat16(v.z), h3 = __float2bfloat16(v.w);
    __nv_bfloat16 l0 = __float2bfloat16(v.x - __bfloat162float(h0));
    __nv_bfloat16 l1 = __float2bfloat16(v.y - __bfloat162float(h1));
    __nv_bfloat16 l2 = __float2bfloat16(v.z - __bfloat162float(h2));
    __nv_bfloat16 l3 = __float2bfloat16(v.w - __bfloat162float(h3));
    uint2 H, L;
    H.x = (uint32_t)__bfloat16_as_ushort(h0) | ((uint32_t)__bfloat16_as_ushort(h1) << 16);
    H.y = (uint32_t)__bfloat16_as_ushort(h2) | ((uint32_t)__bfloat16_as_ushort(h3) << 16);
    L.x = (uint32_t)__bfloat16_as_ushort(l0) | ((uint32_t)__bfloat16_as_ushort(l1) << 16);
    L.y = (uint32_t)__bfloat16_as_ushort(l2) | ((uint32_t)__bfloat16_as_ushort(l3) << 16);
    hi[i] = H; lo[i] = L;
}

// ---------------- broadcast final state (hi+lo -> fp32) ---------------------
__global__ void bcast_kernel(const uint2* __restrict__ hi, const uint2* __restrict__ lo,
                             float4* __restrict__ out)
{
    int i = blockIdx.x * blockDim.x + threadIdx.x;
    int b  = i >> 16;
    int s4 = i & 255;
    uint2 H = hi[(b << 8) + s4];
    uint2 L = lo[(b << 8) + s4];
    float4 o;
    o.x = __bfloat162float(__ushort_as_bfloat16((unsigned short)(H.x & 0xFFFF)))
        + __bfloat162float(__ushort_as_bfloat16((unsigned short)(L.x & 0xFFFF)));
    o.y = __bfloat162float(__ushort_as_bfloat16((unsigned short)(H.x >> 16)))
        + __bfloat162float(__ushort_as_bfloat16((unsigned short)(L.x >> 16)));
    o.z = __bfloat162float(__ushort_as_bfloat16((unsigned short)(H.y & 0xFFFF)))
        + __bfloat162float(__ushort_as_bfloat16((unsigned short)(L.y & 0xFFFF)));
    o.w = __bfloat162float(__ushort_as_bfloat16((unsigned short)(H.y >> 16)))
        + __bfloat162float(__ushort_as_bfloat16((unsigned short)(L.y >> 16)));
    out[i] = o;
}

// ---------------- driver ----------------------------------------------------
extern "C" void kernel_launch(void* const* d_in, const int* in_sizes, int n_in,
                              void* d_out, int out_size)
{
    const float* x      = (const float*)d_in[0];
    const float* W_in   = (const float*)d_in[1];
    const float* b_in   = (const float*)d_in[2];
    const float* W_rec  = (const float*)d_in[3];
    const float* b_rec  = (const float*)d_in[4];
    const float* W_rec2 = (const float*)d_in[5];
    const float* b_rec2 = (const float*)d_in[6];
    float* out = (float*)d_out;

    float* ext;
    __nv_bfloat16 *sAh, *sAl, *sBh, *sBl, *W1h, *W1l, *W2h, *W2l;
    cudaGetSymbolAddress((void**)&ext, g_ext);
    cudaGetSymbolAddress((void**)&sAh, g_sAh);
    cudaGetSymbolAddress((void**)&sAl, g_sAl);
    cudaGetSymbolAddress((void**)&sBh, g_sBh);
    cudaGetSymbolAddress((void**)&sBl, g_sBl);
    cudaGetSymbolAddress((void**)&W1h, g_W1h);
    cudaGetSymbolAddress((void**)&W1l, g_W1l);
    cudaGetSymbolAddress((void**)&W2h, g_W2h);
    cudaGetSymbolAddress((void**)&W2l, g_W2l);

    cudaFuncSetAttribute(layer_kernel, cudaFuncAttributeMaxDynamicSharedMemorySize, SM_TOTAL);

    // Weight hi/lo splits
    split_kernel<<<(SS * SS / 4) / 256, 256>>>((const float4*)W_rec,  (uint2*)W1h, (uint2*)W1l, SS * SS / 4);
    split_kernel<<<(SS * SS / 4) / 256, 256>>>((const float4*)W_rec2, (uint2*)W2h, (uint2*)W2l, SS * SS / 4);

    // Phase 1: ext[t][b][s] = x @ W_in^T + b_in (fp32)
    {
        dim3 grid((BB * TT) / 32, SS / 64);
        proj_kernel<IND><<<grid, 256>>>(x, W_in, b_in, ext);
    }

    // Initial state: s0 = 0 + ext[0]
    split_kernel<<<(BB * SS / 4) / 256, 256>>>((const float4*)ext, (uint2*)sAh, (uint2*)sAl, BB * SS / 4);

    // Phase 2: 256 steps x 2 layers
    {
        dim3 grid(BB / M_TILE, SS / N_TILE);   // (8, 16) = 128 CTAs
        for (int t = 0; t < TT; t++) {
            layer_kernel<<<grid, 128, SM_TOTAL>>>(sAh, sAl, W1h, W1l, b_rec, nullptr, sBh, sBl);
            const float* en = (t < TT - 1) ? (ext + (size_t)(t + 1) * BB * SS) : nullptr;
            layer_kernel<<<grid, 128, SM_TOTAL>>>(sBh, sBl, W2h, W2l, b_rec2, en, sAh, sAl);
        }
    }

    // Phase 3: broadcast final state
    bcast_kernel<<<(BB * TT * SS / 4) / 256, 256>>>((const uint2*)sAh, (const uint2*)sAl, (float4*)out);
}

// round 4
// speedup vs baseline: 4.4766x; 1.3689x over previous
#include <cuda_runtime.h>
#include <cuda_bf16.h>
#include <cstdint>

// Problem dims
#define BB  256
#define TT  256
#define IND 128
#define SS  1024

// ---------------- scratch (__device__ globals) ------------------------------
__device__ float g_ext[(size_t)TT * BB * SS];            // [t][b][s] fp32
__device__ __nv_bfloat16 g_sAh[BB * SS], g_sAl[BB * SS];
__device__ __nv_bfloat16 g_sBh[BB * SS], g_sBl[BB * SS];
__device__ __nv_bfloat16 g_W1h[SS * SS], g_W1l[SS * SS];
__device__ __nv_bfloat16 g_W2h[SS * SS], g_W2l[SS * SS];
__device__ __nv_bfloat16 g_xh[(size_t)BB * TT * IND], g_xl[(size_t)BB * TT * IND];
__device__ __nv_bfloat16 g_Winh[SS * IND], g_Winl[SS * IND];

// ---------------- helpers ---------------------------------------------------
__device__ __forceinline__ uint32_t smem_u32(const void* p) {
    uint32_t a;
    asm("{ .reg .u64 t; cvta.to.shared.u64 t, %1; cvt.u32.u64 %0, t; }" : "=r"(a) : "l"(p));
    return a;
}
__device__ __forceinline__ void cp16(uint32_t dst, const void* src) {
    asm volatile("cp.async.cg.shared.global [%0], [%1], 16;" :: "r"(dst), "l"(src));
}
__device__ __forceinline__ void cp_commit() { asm volatile("cp.async.commit_group;"); }
__device__ __forceinline__ void cp_wait0()  { asm volatile("cp.async.wait_group 0;"); }
__device__ __forceinline__ void cp_wait1()  { asm volatile("cp.async.wait_group 1;"); }

__device__ __forceinline__ void mma16816(float* c, const uint32_t* a,
                                         uint32_t b0, uint32_t b1) {
    asm volatile(
        "mma.sync.aligned.m16n8k16.row.col.f32.bf16.bf16.f32 "
        "{%0,%1,%2,%3}, {%4,%5,%6,%7}, {%8,%9}, {%0,%1,%2,%3};"
        : "+f"(c[0]), "+f"(c[1]), "+f"(c[2]), "+f"(c[3])
        : "r"(a[0]), "r"(a[1]), "r"(a[2]), "r"(a[3]), "r"(b0), "r"(b1));
}
__device__ __forceinline__ void ldsm_x4(uint32_t* r, uint32_t addr) {
    asm volatile("ldmatrix.sync.aligned.m8n8.x4.shared.b16 {%0,%1,%2,%3}, [%4];"
                 : "=r"(r[0]), "=r"(r[1]), "=r"(r[2]), "=r"(r[3]) : "r"(addr));
}

// ---------------- layer GEMM ------------------------------------------------
// O = relu((Ah+Al)(Wh+Wl)^T + bias) (+ ext_next), 3-term bf16, fp32 accum.
// CTA tile 32x64, KC=64, 2-stage cp.async, 256 threads, warp tile 16x16,
// ldmatrix fragment loads, XOR-swizzled SMEM (16B unit ^ (row&7)).
#define M_TILE 32
#define N_TILE 64
#define KC     64
#define NCHUNK (SS / KC)          // 16
#define A_HI 0
#define A_LO 4096
#define B_HI 8192
#define B_LO 16384
#define STAGE_BYTES 24576
#define SM_TOTAL (2 * STAGE_BYTES)   // 49152

__device__ __forceinline__ void load_chunk(
    uint32_t st, int kc0, int tid, int m0, int n0,
    const __nv_bfloat16* __restrict__ Ah, const __nv_bfloat16* __restrict__ Al,
    const __nv_bfloat16* __restrict__ Wh, const __nv_bfloat16* __restrict__ Wl)
{
    #pragma unroll
    for (int i = 0; i < 6; i++) {
        int u = tid + (i << 8);              // 0..1535
        const __nv_bfloat16* src;
        uint32_t dst;
        if (u < 512) {                       // A hi (0..255), A lo (256..511)
            int sel = u >> 8, v = u & 255;
            int row = v >> 3, cu = v & 7;
            src = (sel ? Al : Ah) + (size_t)(m0 + row) * SS + kc0 + cu * 8;
            dst = st + (sel ? A_LO : A_HI) + row * 128 + ((cu ^ (row & 7)) << 4);
        } else {                             // B hi (512..1023), B lo (1024..1535)
            int w = u - 512;
            int sel = w >> 9, v = w & 511;
            int row = v >> 3, cu = v & 7;
            src = (sel ? Wl : Wh) + (size_t)(n0 + row) * SS + kc0 + cu * 8;
            dst = st + (sel ? B_LO : B_HI) + row * 128 + ((cu ^ (row & 7)) << 4);
        }
        cp16(dst, src);
    }
    cp_commit();
}

__global__ __launch_bounds__(256) void layer_kernel(
    const __nv_bfloat16* __restrict__ Ah, const __nv_bfloat16* __restrict__ Al,
    const __nv_bfloat16* __restrict__ Wh, const __nv_bfloat16* __restrict__ Wl,
    const float* __restrict__ bias, const float* __restrict__ ext_next,
    __nv_bfloat16* __restrict__ Oh, __nv_bfloat16* __restrict__ Ol)
{
    extern __shared__ char smem[];
    const uint32_t sb = smem_u32(smem);
    const int tid = threadIdx.x;
    const int wid = tid >> 5, lane = tid & 31;
    const int g = lane >> 2, t4 = lane & 3;
    const int wm = (wid >> 2) << 4;          // 0/16
    const int wn = (wid & 3) << 4;           // 0/16/32/48
    const int m0 = blockIdx.x * M_TILE, n0 = blockIdx.y * N_TILE;

    // ldmatrix lane->row mapping (x4: lanes 0-7 t0, 8-15 t1, 16-23 t2, 24-31 t3)
    const int lr = lane & 7;
    const int half8 = (lane >> 3) & 1;       // +8 rows for tiles 1,3
    const int khalf = (lane >> 4) & 1;       // +8 k for tiles 2,3
    const int rowA = wm + half8 * 8 + lr;
    const int rowB = wn + half8 * 8 + lr;
    const int swA = rowA & 7, swB = rowB & 7;
    const uint32_t aH0 = sb + A_HI + rowA * 128;
    const uint32_t aL0 = sb + A_LO + rowA * 128;
    const uint32_t bH0 = sb + B_HI + rowB * 128;
    const uint32_t bL0 = sb + B_LO + rowB * 128;

    float acc[2][4] = {};

    load_chunk(sb, 0, tid, m0, n0, Ah, Al, Wh, Wl);

    #pragma unroll 1
    for (int c = 0; c < NCHUNK; c++) {
        if (c + 1 < NCHUNK) {
            load_chunk(sb + ((c + 1) & 1) * STAGE_BYTES, (c + 1) * KC,
                       tid, m0, n0, Ah, Al, Wh, Wl);
            cp_wait1();
        } else {
            cp_wait0();
        }
        __syncthreads();

        const uint32_t stg = (c & 1) * STAGE_BYTES;
        #pragma unroll
        for (int ks = 0; ks < 4; ks++) {
            const int u = ks * 2 + khalf;
            uint32_t ah[4], al[4], bh[4], bl[4];
            ldsm_x4(ah, aH0 + stg + ((u ^ swA) << 4));
            ldsm_x4(al, aL0 + stg + ((u ^ swA) << 4));
            ldsm_x4(bh, bH0 + stg + ((u ^ swB) << 4));
            ldsm_x4(bl, bL0 + stg + ((u ^ swB) << 4));
            // j=0: n 0-7 (regs 0,2); j=1: n 8-15 (regs 1,3)
            mma16816(acc[0], ah, bh[0], bh[2]);
            mma16816(acc[0], ah, bl[0], bl[2]);
            mma16816(acc[0], al, bh[0], bh[2]);
            mma16816(acc[1], ah, bh[1], bh[3]);
            mma16816(acc[1], ah, bl[1], bl[3]);
            mma16816(acc[1], al, bh[1], bh[3]);
        }
        __syncthreads();
    }

    // Epilogue: bias + relu (+ ext_next) + hi/lo split + store
    const int row0 = m0 + wm + g;
    const int row1 = row0 + 8;
    #pragma unroll
    for (int j = 0; j < 2; j++) {
        const int col = n0 + wn + j * 8 + t4 * 2;
        float2 bb = *(const float2*)(bias + col);
        float v00 = fmaxf(acc[j][0] + bb.x, 0.0f);
        float v01 = fmaxf(acc[j][1] + bb.y, 0.0f);
        float v10 = fmaxf(acc[j][2] + bb.x, 0.0f);
        float v11 = fmaxf(acc[j][3] + bb.y, 0.0f);
        if (ext_next) {
            float2 e0 = *(const float2*)(ext_next + (size_t)row0 * SS + col);
            float2 e1 = *(const float2*)(ext_next + (size_t)row1 * SS + col);
            v00 += e0.x; v01 += e0.y; v10 += e1.x; v11 += e1.y;
        }
        __nv_bfloat16 h00 = __float2bfloat16(v00), h01 = __float2bfloat16(v01);
        __nv_bfloat16 h10 = __float2bfloat16(v10), h11 = __float2bfloat16(v11);
        __nv_bfloat16 l00 = __float2bfloat16(v00 - __bfloat162float(h00));
        __nv_bfloat16 l01 = __float2bfloat16(v01 - __bfloat162float(h01));
        __nv_bfloat16 l10 = __float2bfloat16(v10 - __bfloat162float(h10));
        __nv_bfloat16 l11 = __float2bfloat16(v11 - __bfloat162float(h11));
        *(uint32_t*)(Oh + (size_t)row0 * SS + col) =
            (uint32_t)__bfloat16_as_ushort(h00) | ((uint32_t)__bfloat16_as_ushort(h01) << 16);
        *(uint32_t*)(Oh + (size_t)row1 * SS + col) =
            (uint32_t)__bfloat16_as_ushort(h10) | ((uint32_t)__bfloat16_as_ushort(h11) << 16);
        *(uint32_t*)(Ol + (size_t)row0 * SS + col) =
            (uint32_t)__bfloat16_as_ushort(l00) | ((uint32_t)__bfloat16_as_ushort(l01) << 16);
        *(uint32_t*)(Ol + (size_t)row1 * SS + col) =
            (uint32_t)__bfloat16_as_ushort(l10) | ((uint32_t)__bfloat16_as_ushort(l11) << 16);
    }
}

// ---------------- input projection (bf16 3-term MMA) ------------------------
// ext[t][b][n] = x[b*T+t, :] @ W_in^T + b_in, fp32 out. CTA 64x64, K=128 one shot.
#define PA_HI 0
#define PA_LO 16384
#define PB_HI 32768
#define PB_LO 49152
#define P_SM  65536

__global__ __launch_bounds__(256) void proj_mma(
    const __nv_bfloat16* __restrict__ Xh, const __nv_bfloat16* __restrict__ Xl,
    const __nv_bfloat16* __restrict__ Wh, const __nv_bfloat16* __restrict__ Wl,
    const float* __restrict__ bias, float* __restrict__ Out)
{
    extern __shared__ char smem[];
    const uint32_t sb = smem_u32(smem);
    const int tid = threadIdx.x;
    const int wid = tid >> 5, lane = tid & 31;
    const int g = lane >> 2, t4 = lane & 3;
    const int wm = (wid >> 1) << 4;          // 0..48
    const int wn = (wid & 1) << 5;           // 0/32
    const int m0 = blockIdx.x * 64, n0 = blockIdx.y * 64;

    // Load A (x) and B (W_in), K=128, pitch 256B = 16 units, swizzle low 3 bits
    #pragma unroll
    for (int i = 0; i < 16; i++) {
        int u = tid + (i << 8);              // 0..4095
        const __nv_bfloat16* src;
        uint32_t dst;
        if (u < 2048) {
            int sel = u >> 10, v = u & 1023;
            int row = v >> 4, cu = v & 15;
            src = (sel ? Xl : Xh) + (size_t)(m0 + row) * IND + cu * 8;
            dst = sb + (sel ? PA_LO : PA_HI) + row * 256
                + (((cu & 8) | ((cu & 7) ^ (row & 7))) << 4);
        } else {
            int w = u - 2048;
            int sel = w >> 10, v = w & 1023;
            int row = v >> 4, cu = v & 15;
            src = (sel ? Wl : Wh) + (size_t)(n0 + row) * IND + cu * 8;
            dst = sb + (sel ? PB_LO : PB_HI) + row * 256
                + (((cu & 8) | ((cu & 7) ^ (row & 7))) << 4);
        }
        cp16(dst, src);
    }
    cp_commit();
    cp_wait0();
    __syncthreads();

    const int lr = lane & 7;
    const int half8 = (lane >> 3) & 1;
    const int khalf = (lane >> 4) & 1;
    const int rowA = wm + half8 * 8 + lr;
    const int rowB = wn + half8 * 8 + lr;    // jj=1 adds +16
    const int swA = rowA & 7, swB = rowB & 7;

    float acc[4][4] = {};
    #pragma unroll
    for (int ks = 0; ks < 8; ks++) {
        const int u = ks * 2 + khalf;        // 0..15
        const uint32_t puA = (((u & 8) | ((u & 7) ^ swA)) << 4);
        const uint32_t puB = (((u & 8) | ((u & 7) ^ swB)) << 4);
        uint32_t ah[4], al[4];
        ldsm_x4(ah, sb + PA_HI + rowA * 256 + puA);
        ldsm_x4(al, sb + PA_LO + rowA * 256 + puA);
        #pragma unroll
        for (int jj = 0; jj < 2; jj++) {
            uint32_t bh[4], bl[4];
            ldsm_x4(bh, sb + PB_HI + (rowB + jj * 16) * 256 + puB);
            ldsm_x4(bl, sb + PB_LO + (rowB + jj * 16) * 256 + puB);
            mma16816(acc[jj * 2],     ah, bh[0], bh[2]);
            mma16816(acc[jj * 2],     ah, bl[0], bl[2]);
            mma16816(acc[jj * 2],     al, bh[0], bh[2]);
            mma16816(acc[jj * 2 + 1], ah, bh[1], bh[3]);
            mma16816(acc[jj * 2 + 1], ah, bl[1], bl[3]);
            mma16816(acc[jj * 2 + 1], al, bh[1], bh[3]);
        }
    }

    // Epilogue: + bias, remap m=b*T+t -> ext[t][b][:], fp32 stores
    const int r0 = m0 + wm + g;
    const int r1 = r0 + 8;
    const int b0r = r0 >> 8, t0r = r0 & 255;
    const int b1r = r1 >> 8, t1r = r1 & 255;
    #pragma unroll
    for (int j = 0; j < 4; j++) {
        const int col = n0 + wn + j * 8 + t4 * 2;
        float2 bb = *(const float2*)(bias + col);
        float2 o0 = make_float2(acc[j][0] + bb.x, acc[j][1] + bb.y);
        float2 o1 = make_float2(acc[j][2] + bb.x, acc[j][3] + bb.y);
        *(float2*)(Out + ((size_t)t0r * BB + b0r) * SS + col) = o0;
        *(float2*)(Out + ((size_t)t1r * BB + b1r) * SS + col) = o1;
    }
}

// ---------------- hi/lo split of a float array ------------------------------
__global__ void split_kernel(const float4* __restrict__ in,
                             uint2* __restrict__ hi, uint2* __restrict__ lo, int n4)
{
    int i = blockIdx.x * blockDim.x + threadIdx.x;
    if (i >= n4) return;
    float4 v = in[i];
    __nv_bfloat16 h0 = __float2bfloat16(v.x), h1 = __float2bfloat16(v.y);
    __nv_bfloat16 h2 = __float2bfloat16(v.z), h3 = __float2bfloat16(v.w);
    __nv_bfloat16 l0 = __float2bfloat16(v.x - __bfloat162float(h0));
    __nv_bfloat16 l1 = __float2bfloat16(v.y - __bfloat162float(h1));
    __nv_bfloat16 l2 = __float2bfloat16(v.z - __bfloat162float(h2));
    __nv_bfloat16 l3 = __float2bfloat16(v.w - __bfloat162float(h3));
    uint2 H, L;
    H.x = (uint32_t)__bfloat16_as_ushort(h0) | ((uint32_t)__bfloat16_as_ushort(h1) << 16);
    H.y = (uint32_t)__bfloat16_as_ushort(h2) | ((uint32_t)__bfloat16_as_ushort(h3) << 16);
    L.x = (uint32_t)__bfloat16_as_ushort(l0) | ((uint32_t)__bfloat16_as_ushort(l1) << 16);
    L.y = (uint32_t)__bfloat16_as_ushort(l2) | ((uint32_t)__bfloat16_as_ushort(l3) << 16);
    hi[i] = H; lo[i] = L;
}

// ---------------- broadcast final state (hi+lo -> fp32) ---------------------
__global__ void bcast_kernel(const uint2* __restrict__ hi, const uint2* __restrict__ lo,
                             float4* __restrict__ out)
{
    int i = blockIdx.x * blockDim.x + threadIdx.x;
    int b  = i >> 16;
    int s4 = i & 255;
    uint2 H = hi[(b << 8) + s4];
    uint2 L = lo[(b << 8) + s4];
    float4 o;
    o.x = __bfloat162float(__ushort_as_bfloat16((unsigned short)(H.x & 0xFFFF)))
        + __bfloat162float(__ushort_as_bfloat16((unsigned short)(L.x & 0xFFFF)));
    o.y = __bfloat162float(__ushort_as_bfloat16((unsigned short)(H.x >> 16)))
        + __bfloat162float(__ushort_as_bfloat16((unsigned short)(L.x >> 16)));
    o.z = __bfloat162float(__ushort_as_bfloat16((unsigned short)(H.y & 0xFFFF)))
        + __bfloat162float(__ushort_as_bfloat16((unsigned short)(L.y & 0xFFFF)));
    o.w = __bfloat162float(__ushort_as_bfloat16((unsigned short)(H.y >> 16)))
        + __bfloat162float(__ushort_as_bfloat16((unsigned short)(L.y >> 16)));
    out[i] = o;
}

// ---------------- driver ----------------------------------------------------
extern "C" void kernel_launch(void* const* d_in, const int* in_sizes, int n_in,
                              void* d_out, int out_size)
{
    const float* x      = (const float*)d_in[0];
    const float* W_in   = (const float*)d_in[1];
    const float* b_in   = (const float*)d_in[2];
    const float* W_rec  = (const float*)d_in[3];
    const float* b_rec  = (const float*)d_in[4];
    const float* W_rec2 = (const float*)d_in[5];
    const float* b_rec2 = (const float*)d_in[6];
    float* out = (float*)d_out;

    float* ext;
    __nv_bfloat16 *sAh, *sAl, *sBh, *sBl, *W1h, *W1l, *W2h, *W2l;
    __nv_bfloat16 *xh, *xl, *Winh, *Winl;
    cudaGetSymbolAddress((void**)&ext, g_ext);
    cudaGetSymbolAddress((void**)&sAh, g_sAh);
    cudaGetSymbolAddress((void**)&sAl, g_sAl);
    cudaGetSymbolAddress((void**)&sBh, g_sBh);
    cudaGetSymbolAddress((void**)&sBl, g_sBl);
    cudaGetSymbolAddress((void**)&W1h, g_W1h);
    cudaGetSymbolAddress((void**)&W1l, g_W1l);
    cudaGetSymbolAddress((void**)&W2h, g_W2h);
    cudaGetSymbolAddress((void**)&W2l, g_W2l);
    cudaGetSymbolAddress((void**)&xh,  g_xh);
    cudaGetSymbolAddress((void**)&xl,  g_xl);
    cudaGetSymbolAddress((void**)&Winh, g_Winh);
    cudaGetSymbolAddress((void**)&Winl, g_Winl);

    cudaFuncSetAttribute(layer_kernel, cudaFuncAttributeMaxDynamicSharedMemorySize, SM_TOTAL);
    cudaFuncSetAttribute(proj_mma,     cudaFuncAttributeMaxDynamicSharedMemorySize, P_SM);

    // hi/lo splits
    split_kernel<<<(SS * SS / 4) / 256, 256>>>((const float4*)W_rec,  (uint2*)W1h, (uint2*)W1l, SS * SS / 4);
    split_kernel<<<(SS * SS / 4) / 256, 256>>>((const float4*)W_rec2, (uint2*)W2h, (uint2*)W2l, SS * SS / 4);
    split_kernel<<<((size_t)BB * TT * IND / 4 + 255) / 256, 256>>>(
        (const float4*)x, (uint2*)xh, (uint2*)xl, BB * TT * IND / 4);
    split_kernel<<<(SS * IND / 4 + 255) / 256, 256>>>(
        (const float4*)W_in, (uint2*)Winh, (uint2*)Winl, SS * IND / 4);

    // Phase 1: ext = x @ W_in^T + b_in (bf16 3-term MMA, fp32 out)
    {
        dim3 grid((BB * TT) / 64, SS / 64);   // (1024, 16)
        proj_mma<<<grid, 256, P_SM>>>(xh, xl, Winh, Winl, b_in, ext);
    }

    // Initial state: s0 = 0 + ext[0]
    split_kernel<<<(BB * SS / 4) / 256, 256>>>((const float4*)ext, (uint2*)sAh, (uint2*)sAl, BB * SS / 4);

    // Phase 2: 256 steps x 2 layers
    {
        dim3 grid(BB / M_TILE, SS / N_TILE);   // (8, 16) = 128 CTAs
        for (int t = 0; t < TT; t++) {
            layer_kernel<<<grid, 256, SM_TOTAL>>>(sAh, sAl, W1h, W1l, b_rec, nullptr, sBh, sBl);
            const float* en = (t < TT - 1) ? (ext + (size_t)(t + 1) * BB * SS) : nullptr;
            layer_kernel<<<grid, 256, SM_TOTAL>>>(sBh, sBl, W2h, W2l, b_rec2, en, sAh, sAl);
        }
    }

    // Phase 3: broadcast final state
    bcast_kernel<<<(BB * TT * SS / 4) / 256, 256>>>((const uint2*)sAh, (const uint2*)sAl, (float4*)out);
}